// round 2
// baseline (speedup 1.0000x reference)
#include <cuda_runtime.h>

#define B_  128
#define T_  256
#define R_  1024
#define NU_ 256
#define BR_ (B_*R_)

// ---------------- static device scratch (no allocations allowed) ----------------
__device__ float g_xh[(size_t)T_*BR_];    // [t][b][r]  x@Wh0x + bh0
__device__ float g_xt[(size_t)T_*BR_];    // [t][b][r]  x@Wt0x + bt0
__device__ float g_hist[(size_t)T_*BR_];  // [t][b][r]  state after step t
__device__ float g_sA[BR_];
__device__ float g_sB[BR_];
__device__ float g_s0[BR_];               // stays zero (initial state)

typedef unsigned long long u64;

// ---------------- packed f32x2 helpers (full-rate fp32 FMA on sm_103a) ----------
__device__ __forceinline__ u64 pk2(float lo, float hi) {
    u64 r; asm("mov.b64 %0, {%1, %2};" : "=l"(r) : "f"(lo), "f"(hi)); return r;
}
__device__ __forceinline__ void up2(float &lo, float &hi, u64 v) {
    asm("mov.b64 {%0, %1}, %2;" : "=f"(lo), "=f"(hi) : "l"(v));
}
__device__ __forceinline__ void fma2(u64 &d, u64 a, u64 b) {
    asm("fma.rn.f32x2 %0, %1, %2, %0;" : "+l"(d) : "l"(a), "l"(b));
}

__device__ __forceinline__ float sigmoid_(float x) {
    return __frcp_rn(1.f + __expf(-x));
}
__device__ __forceinline__ float tanh_(float x) {
    return __fmaf_rn(2.f, __frcp_rn(1.f + __expf(-2.f*x)), -1.f);
}

// =================================================================================
// Stage kernel: one highway layer for one timestep.
//   s_out[m,n] = (tanh(s@Wh + ah) - s) * sigmoid(s@Wt + at) + s
// ah/at: ah[m*add_stride + n] (stride=R for per-element xh/xt, 0 for bias rows).
// Block: 128 m-rows x 8 n-cols, both gates. Grid = 128 blocks. 256 threads.
// =================================================================================
#define KB 64
__global__ __launch_bounds__(256, 1) void stage_kernel(
    const float* __restrict__ s_in,
    const float* __restrict__ Wh, const float* __restrict__ Wt,
    const float* __restrict__ addh, const float* __restrict__ addt,
    int add_stride,
    float* __restrict__ s_out)
{
    __shared__ float s_sm[KB*130];   // [k_local][m], pitch 130 (even -> u64 ok)
    __shared__ u64 wh_sm[KB*8];      // pre-duplicated {w,w}
    __shared__ u64 wt_sm[KB*8];

    const int tid = threadIdx.x;
    const int n0  = blockIdx.x * 8;
    const int mp  = tid & 63;        // 2 m-rows each: m0 = 2*mp
    const int np  = tid >> 6;        // 0..3 -> 2 n-cols each

    u64 ah0 = 0, ah1 = 0, at0 = 0, at1 = 0;

    for (int k0 = 0; k0 < R_; k0 += KB) {
        // ---- load s chunk [128 m][KB k], transposed to [k][m] ----
        #pragma unroll
        for (int it = 0; it < (128*KB/4)/256; ++it) {
            int idx = tid + it*256;
            int m = idx >> 4, q = idx & 15;
            float4 v = *(const float4*)(s_in + (size_t)m*R_ + k0 + 4*q);
            s_sm[(4*q+0)*130 + m] = v.x;
            s_sm[(4*q+1)*130 + m] = v.y;
            s_sm[(4*q+2)*130 + m] = v.z;
            s_sm[(4*q+3)*130 + m] = v.w;
        }
        // ---- load weight chunks (KB x 8 each), duplicated into f32x2 ----
        #pragma unroll
        for (int it = 0; it < 2; ++it) {
            int idx = tid + it*256;
            int kl = idx >> 3, c = idx & 7;
            float wh = Wh[(size_t)(k0+kl)*R_ + n0 + c];
            float wt = Wt[(size_t)(k0+kl)*R_ + n0 + c];
            wh_sm[kl*8 + c] = pk2(wh, wh);
            wt_sm[kl*8 + c] = pk2(wt, wt);
        }
        __syncthreads();

        // ---- FFMA2 mainloop: 7 instr / 4 FFMA2 per k ----
        #pragma unroll 16
        for (int kl = 0; kl < KB; ++kl) {
            u64 s2 = *(const u64*)&s_sm[kl*130 + 2*mp];
            ulonglong2 wh = *(const ulonglong2*)&wh_sm[kl*8 + 2*np];
            ulonglong2 wt = *(const ulonglong2*)&wt_sm[kl*8 + 2*np];
            fma2(ah0, s2, wh.x);
            fma2(ah1, s2, wh.y);
            fma2(at0, s2, wt.x);
            fma2(at1, s2, wt.y);
        }
        __syncthreads();
    }

    // ---- epilogue: highway update ----
    const int m0 = 2*mp;
    #pragma unroll
    for (int j = 0; j < 2; ++j) {
        int n = n0 + 2*np + j;
        float h_lo, h_hi, t_lo, t_hi;
        up2(h_lo, h_hi, j ? ah1 : ah0);
        up2(t_lo, t_hi, j ? at1 : at0);
        float hacc[2] = {h_lo, h_hi};
        float tacc[2] = {t_lo, t_hi};
        #pragma unroll
        for (int i = 0; i < 2; ++i) {
            int m = m0 + i;
            float ah = addh[(size_t)m*add_stride + n];
            float at = addt[(size_t)m*add_stride + n];
            float sv = s_in[(size_t)m*R_ + n];
            float h  = tanh_(hacc[i] + ah);
            float tg = sigmoid_(tacc[i] + at);
            s_out[(size_t)m*R_ + n] = (h - sv)*tg + sv;
        }
    }
}

// =================================================================================
// Pre kernel: xh = emb[tok]@Wh0x + bh0 ; xt = emb[tok]@Wt0x + bt0, stored [t][b][r].
// Block: 32 rows (rho = t*B+b) x 64 r-cols, both gates. Grid (16, 1024). 256 thr.
// =================================================================================
#define KBP 8
__global__ __launch_bounds__(256, 1) void pre_kernel(
    const int* __restrict__ tok, const float* __restrict__ emb,
    const float* __restrict__ Whx, const float* __restrict__ Wtx,
    const float* __restrict__ bh, const float* __restrict__ bt)
{
    __shared__ float x_sm[NU_*34];     // [k][row], 256 x 32, pitch 34
    __shared__ u64 wh_sm[KBP*64];
    __shared__ u64 wt_sm[KBP*64];

    const int tid  = threadIdx.x;
    const int row0 = blockIdx.y * 32;
    const int n0   = blockIdx.x * 64;

    // gather x tile: 32 rows x 256 k, transposed
    #pragma unroll
    for (int it = 0; it < 8; ++it) {
        int idx = tid + it*256;
        int r = idx >> 6, q = idx & 63;
        int rho = row0 + r;
        int b = rho & (B_-1), t = rho >> 7;
        int token = tok[b*T_ + t];
        float4 v = *(const float4*)(emb + (size_t)token*NU_ + 4*q);
        x_sm[(4*q+0)*34 + r] = v.x;
        x_sm[(4*q+1)*34 + r] = v.y;
        x_sm[(4*q+2)*34 + r] = v.z;
        x_sm[(4*q+3)*34 + r] = v.w;
    }
    __syncthreads();

    const int mp = tid & 15;   // 2 rows each
    const int ng = tid >> 4;   // 0..15 -> 4 cols each
    u64 acch[4] = {0,0,0,0};
    u64 acct[4] = {0,0,0,0};

    for (int k0 = 0; k0 < NU_; k0 += KBP) {
        #pragma unroll
        for (int it = 0; it < 2; ++it) {
            int idx = tid + it*256;
            int kl = idx >> 6, c = idx & 63;
            float wh = Whx[(size_t)(k0+kl)*R_ + n0 + c];
            float wt = Wtx[(size_t)(k0+kl)*R_ + n0 + c];
            wh_sm[kl*64 + c] = pk2(wh, wh);
            wt_sm[kl*64 + c] = pk2(wt, wt);
        }
        __syncthreads();
        #pragma unroll
        for (int kl = 0; kl < KBP; ++kl) {
            u64 x2 = *(const u64*)&x_sm[(k0+kl)*34 + 2*mp];
            ulonglong2 wa = *(const ulonglong2*)&wh_sm[kl*64 + 4*ng];
            ulonglong2 wb = *(const ulonglong2*)&wh_sm[kl*64 + 4*ng + 2];
            ulonglong2 ta = *(const ulonglong2*)&wt_sm[kl*64 + 4*ng];
            ulonglong2 tb = *(const ulonglong2*)&wt_sm[kl*64 + 4*ng + 2];
            fma2(acch[0], x2, wa.x); fma2(acch[1], x2, wa.y);
            fma2(acch[2], x2, wb.x); fma2(acch[3], x2, wb.y);
            fma2(acct[0], x2, ta.x); fma2(acct[1], x2, ta.y);
            fma2(acct[2], x2, tb.x); fma2(acct[3], x2, tb.y);
        }
        __syncthreads();
    }

    // epilogue: g_xh/g_xt index = rho*R + n  (== [t][b][r])
    #pragma unroll
    for (int j = 0; j < 4; ++j) {
        int n = n0 + 4*ng + j;
        float lo, hi, tlo, thi;
        up2(lo, hi, acch[j]);
        up2(tlo, thi, acct[j]);
        size_t rbase = (size_t)(row0 + 2*mp) * R_;
        g_xh[rbase + n]       = lo  + bh[n];
        g_xh[rbase + R_ + n]  = hi  + bh[n];
        g_xt[rbase + n]       = tlo + bt[n];
        g_xt[rbase + R_ + n]  = thi + bt[n];
    }
}

// =================================================================================
// Post kernel: out[(b*T+t), n] = hist[t,b,:] @ Wp + bp.
// Block: 32 hist-rows x 64 out-cols. Grid (4, 1024). 256 threads.
// =================================================================================
#define KBQ 32
__global__ __launch_bounds__(256, 1) void post_kernel(
    const float* __restrict__ Wp, const float* __restrict__ bp,
    float* __restrict__ out)
{
    __shared__ float s_sm[KBQ*34];   // [k][row], 32 x 32, pitch 34
    __shared__ u64 w_sm[KBQ*64];

    const int tid  = threadIdx.x;
    const int row0 = blockIdx.y * 32;
    const int n0   = blockIdx.x * 64;
    const int mp = tid & 15;
    const int ng = tid >> 4;
    u64 acc[4] = {0,0,0,0};

    for (int k0 = 0; k0 < R_; k0 += KBQ) {
        {   // 32 rows x 32 k = 256 float4, one per thread
            int r = tid >> 3, q = tid & 7;
            float4 v = *(const float4*)(g_hist + (size_t)(row0+r)*R_ + k0 + 4*q);
            s_sm[(4*q+0)*34 + r] = v.x;
            s_sm[(4*q+1)*34 + r] = v.y;
            s_sm[(4*q+2)*34 + r] = v.z;
            s_sm[(4*q+3)*34 + r] = v.w;
        }
        #pragma unroll
        for (int it = 0; it < 8; ++it) {
            int idx = tid + it*256;
            int kl = idx >> 6, c = idx & 63;
            float w = Wp[(size_t)(k0+kl)*NU_ + n0 + c];
            w_sm[kl*64 + c] = pk2(w, w);
        }
        __syncthreads();
        #pragma unroll 16
        for (int kl = 0; kl < KBQ; ++kl) {
            u64 s2 = *(const u64*)&s_sm[kl*34 + 2*mp];
            ulonglong2 wa = *(const ulonglong2*)&w_sm[kl*64 + 4*ng];
            ulonglong2 wb = *(const ulonglong2*)&w_sm[kl*64 + 4*ng + 2];
            fma2(acc[0], s2, wa.x); fma2(acc[1], s2, wa.y);
            fma2(acc[2], s2, wb.x); fma2(acc[3], s2, wb.y);
        }
        __syncthreads();
    }

    #pragma unroll
    for (int j = 0; j < 4; ++j) {
        int n = n0 + 4*ng + j;
        float lo, hi;
        up2(lo, hi, acc[j]);
        int rho0 = row0 + 2*mp;
        int b0 = rho0 & (B_-1), t0 = rho0 >> 7;
        int rho1 = rho0 + 1;
        int b1 = rho1 & (B_-1), t1 = rho1 >> 7;
        out[(size_t)(b0*T_ + t0)*NU_ + n] = lo + bp[n];
        out[(size_t)(b1*T_ + t1)*NU_ + n] = hi + bp[n];
    }
}

// =================================================================================
extern "C" void kernel_launch(void* const* d_in, const int* in_sizes, int n_in,
                              void* d_out, int out_size) {
    const int*   tok  = (const int*)  d_in[0];
    const float* emb  = (const float*)d_in[1];
    const float* Wh0x = (const float*)d_in[2];
    const float* Wh0s = (const float*)d_in[3];
    const float* bh0  = (const float*)d_in[4];
    const float* Wt0x = (const float*)d_in[5];
    const float* Wt0s = (const float*)d_in[6];
    const float* bt0  = (const float*)d_in[7];
    const float* Whh  = (const float*)d_in[8];
    const float* bhh  = (const float*)d_in[9];
    const float* Wth  = (const float*)d_in[10];
    const float* bth  = (const float*)d_in[11];
    const float* Wp   = (const float*)d_in[12];
    const float* bp   = (const float*)d_in[13];

    float *xh, *xt, *hist, *sA, *sB, *s0;
    cudaGetSymbolAddress((void**)&xh,   g_xh);
    cudaGetSymbolAddress((void**)&xt,   g_xt);
    cudaGetSymbolAddress((void**)&hist, g_hist);
    cudaGetSymbolAddress((void**)&sA,   g_sA);
    cudaGetSymbolAddress((void**)&sB,   g_sB);
    cudaGetSymbolAddress((void**)&s0,   g_s0);

    pre_kernel<<<dim3(16, 1024), 256>>>(tok, emb, Wh0x, Wt0x, bh0, bt0);

    const float* sprev = s0;
    for (int t = 0; t < T_; ++t) {
        // layer 0: per-element xh/xt additions (stride R)
        stage_kernel<<<128, 256>>>(sprev, Wh0s, Wt0s,
                                   xh + (size_t)t*BR_, xt + (size_t)t*BR_, R_, sA);
        // layer 1
        stage_kernel<<<128, 256>>>(sA, Whh, Wth, bhh, bth, 0, sB);
        // layer 2 -> hist[t]
        stage_kernel<<<128, 256>>>(sB, Whh + (size_t)R_*R_, Wth + (size_t)R_*R_,
                                   bhh + R_, bth + R_, 0, hist + (size_t)t*BR_);
        sprev = hist + (size_t)t*BR_;
    }

    post_kernel<<<dim3(4, 1024), 256>>>(Wp, bp, (float*)d_out);
}

// round 3
// speedup vs baseline: 1.3500x; 1.3500x over previous
#include <cuda_runtime.h>

#define B_  128
#define T_  256
#define R_  1024
#define NU_ 256
#define BR_ (B_*R_)

// ---------------- static device scratch (no allocations allowed) ----------------
// NOTE: state tensors are stored TRANSPOSED: [r][b] (r-major), so GEMM smem tiles
// are flat contiguous copies (cp.async-able, no transpose scatter).
__device__ float g_xh[(size_t)T_*BR_];    // [t][r][b]
__device__ float g_xt[(size_t)T_*BR_];    // [t][r][b]
__device__ float g_hist[(size_t)T_*BR_];  // [t][r][b]
__device__ float g_sA[BR_];
__device__ float g_sB[BR_];
__device__ float g_s0[BR_];               // stays zero (initial state)

typedef unsigned long long u64;

// ---------------- packed f32x2 helpers (full-rate fp32 FMA on sm_103a) ----------
__device__ __forceinline__ u64 pk2(float lo, float hi) {
    u64 r; asm("mov.b64 %0, {%1, %2};" : "=l"(r) : "f"(lo), "f"(hi)); return r;
}
__device__ __forceinline__ void up2(float &lo, float &hi, u64 v) {
    asm("mov.b64 {%0, %1}, %2;" : "=f"(lo), "=f"(hi) : "l"(v));
}
__device__ __forceinline__ void fma2(u64 &d, u64 a, u64 b) {
    asm("fma.rn.f32x2 %0, %1, %2, %0;" : "+l"(d) : "l"(a), "l"(b));
}

__device__ __forceinline__ float sigmoid_(float x) {
    return __frcp_rn(1.f + __expf(-x));
}
__device__ __forceinline__ float tanh_(float x) {
    return __fmaf_rn(2.f, __frcp_rn(1.f + __expf(-2.f*x)), -1.f);
}

// ---------------- cp.async helpers ----------------
__device__ __forceinline__ void cp16(unsigned s, const void* g) {
    asm volatile("cp.async.cg.shared.global [%0], [%1], 16;" :: "r"(s), "l"(g));
}
__device__ __forceinline__ void cpcommit() { asm volatile("cp.async.commit_group;"); }
template<int N> __device__ __forceinline__ void cpwait() {
    asm volatile("cp.async.wait_group %0;" :: "n"(N));
}

// =================================================================================
// Stage kernel: one highway layer for one timestep (all tensors [r][b] transposed).
//   s_out[n,m] = (tanh(G_h[n,m] + addh) - s[n,m]) * sigmoid(G_t[n,m] + addt) + s
//   G[n,m] = sum_k s[k,m] * W[k,n]
// Block: 128 m x 8 n, both gates. Grid 128. 256 threads = 8 warps:
//   warp = (gate = w&1, mslice = w>>1 covers 32 m); lane = mg(8 quads) x ng(4 pairs).
// Dynamic smem: s dbuf 2x64KB | w dbuf 2x(8KB h + 8KB t) | 4KB tg exchange.
// =================================================================================
#define KC 128           // k per chunk
#define NCH (R_/KC)      // 8 chunks
#define SM_S(buf)   ((buf)*65536)
#define SM_W(buf,g) (131072 + (buf)*16384 + (g)*8192)
#define SM_TG       163840
#define SM_TOTAL    167936

__global__ __launch_bounds__(256, 1) void stage_kernel(
    const float* __restrict__ s_in,
    const float* __restrict__ Wh, const float* __restrict__ Wt,
    const float* __restrict__ addh, const float* __restrict__ addt,
    int per_elem,
    float* __restrict__ s_out)
{
    extern __shared__ char sm[];
    const int tid    = threadIdx.x;
    const int n0     = blockIdx.x * 8;
    const int warp   = tid >> 5, lane = tid & 31;
    const int gate   = warp & 1, mslice = warp >> 1;
    const int mg     = lane & 7, ng = lane >> 3;
    const int m0     = mslice * 32 + mg * 4;
    const int nc0    = ng * 2;

    // ---- prologue: s chunk 0 via cp.async, w chunk 0 direct ----
    {
        const char* g = (const char*)s_in;
        unsigned sb = (unsigned)__cvta_generic_to_shared(sm + SM_S(0));
        #pragma unroll
        for (int j = 0; j < 16; ++j) {
            int o = (tid + j*256) * 16;
            cp16(sb + o, g + o);
        }
        cpcommit();
        // weights chunk 0: [128 k][8 n] each matrix; 512 float2 / 256 thr = 2 each
        u64* wbh = (u64*)(sm + SM_W(0,0));
        u64* wbt = (u64*)(sm + SM_W(0,1));
        #pragma unroll
        for (int it = 0; it < 2; ++it) {
            int idx = tid + it*256;
            int kl = idx >> 2, cc = idx & 3;
            float2 vh = *(const float2*)(Wh + (size_t)kl*R_ + n0 + 2*cc);
            float2 vt = *(const float2*)(Wt + (size_t)kl*R_ + n0 + 2*cc);
            ulonglong2 dh; dh.x = pk2(vh.x, vh.x); dh.y = pk2(vh.y, vh.y);
            ulonglong2 dt; dt.x = pk2(vt.x, vt.x); dt.y = pk2(vt.y, vt.y);
            *(ulonglong2*)(wbh + kl*8 + 2*cc) = dh;
            *(ulonglong2*)(wbt + kl*8 + 2*cc) = dt;
        }
    }

    u64 acc0 = 0, acc1 = 0, acc2 = 0, acc3 = 0;
    float2 whr[2], wtr[2];

    for (int c = 0; c < NCH; ++c) {
        const int cur = c & 1, nxt = cur ^ 1;
        const bool more = (c + 1 < NCH);
        if (more) {
            // prefetch s chunk c+1
            const char* g = (const char*)(s_in + (size_t)(c+1)*KC*128);
            unsigned sb = (unsigned)__cvta_generic_to_shared(sm + SM_S(nxt));
            #pragma unroll
            for (int j = 0; j < 16; ++j) {
                int o = (tid + j*256) * 16;
                cp16(sb + o, g + o);
            }
            cpcommit();
            // prefetch w chunk c+1 into registers
            #pragma unroll
            for (int it = 0; it < 2; ++it) {
                int idx = tid + it*256;
                int kl = idx >> 2, cc = idx & 3;
                size_t go = (size_t)((c+1)*KC + kl)*R_ + n0 + 2*cc;
                whr[it] = *(const float2*)(Wh + go);
                wtr[it] = *(const float2*)(Wt + go);
            }
        }
        if (more) cpwait<1>(); else cpwait<0>();
        __syncthreads();

        // ---- mainloop: 1 LDS.128 (s) + 1 LDS.128 (w) + 4 FFMA2 per k ----
        {
            const char* sp = sm + SM_S(cur) + m0*4;
            const char* wp = sm + SM_W(cur, gate) + nc0*8;
            #pragma unroll 8
            for (int kl = 0; kl < KC; ++kl) {
                ulonglong2 s2 = *(const ulonglong2*)(sp + kl*512);
                ulonglong2 w2 = *(const ulonglong2*)(wp + kl*64);
                fma2(acc0, s2.x, w2.x);
                fma2(acc1, s2.y, w2.x);
                fma2(acc2, s2.x, w2.y);
                fma2(acc3, s2.y, w2.y);
            }
        }
        __syncthreads();

        if (more) {
            u64* wbh = (u64*)(sm + SM_W(nxt,0));
            u64* wbt = (u64*)(sm + SM_W(nxt,1));
            #pragma unroll
            for (int it = 0; it < 2; ++it) {
                int idx = tid + it*256;
                int kl = idx >> 2, cc = idx & 3;
                ulonglong2 dh; dh.x = pk2(whr[it].x, whr[it].x); dh.y = pk2(whr[it].y, whr[it].y);
                ulonglong2 dt; dt.x = pk2(wtr[it].x, wtr[it].x); dt.y = pk2(wtr[it].y, wtr[it].y);
                *(ulonglong2*)(wbh + kl*8 + 2*cc) = dh;
                *(ulonglong2*)(wbt + kl*8 + 2*cc) = dt;
            }
        }
    }

    // ---- epilogue: t-warps compute sigmoid -> smem; h-warps combine ----
    float a[8];
    up2(a[0], a[1], acc0);   // m0, m0+1   @ n = nc0
    up2(a[2], a[3], acc1);   // m0+2, m0+3 @ n = nc0
    up2(a[4], a[5], acc2);   // m0, m0+1   @ n = nc0+1
    up2(a[6], a[7], acc3);   // m0+2, m0+3 @ n = nc0+1

    float* tg = (float*)(sm + SM_TG);

    if (gate == 1) {
        #pragma unroll
        for (int j = 0; j < 2; ++j) {
            int n = n0 + nc0 + j;
            float ad0, ad1, ad2, ad3;
            if (per_elem) {
                float4 t4 = *(const float4*)(addt + (size_t)n*128 + m0);
                ad0 = t4.x; ad1 = t4.y; ad2 = t4.z; ad3 = t4.w;
            } else {
                ad0 = ad1 = ad2 = ad3 = addt[n];
            }
            float4 o;
            o.x = sigmoid_(a[4*j+0] + ad0);
            o.y = sigmoid_(a[4*j+1] + ad1);
            o.z = sigmoid_(a[4*j+2] + ad2);
            o.w = sigmoid_(a[4*j+3] + ad3);
            *(float4*)&tg[(nc0+j)*128 + m0] = o;
        }
    }
    __syncthreads();
    if (gate == 0) {
        #pragma unroll
        for (int j = 0; j < 2; ++j) {
            int n = n0 + nc0 + j;
            float ad0, ad1, ad2, ad3;
            if (per_elem) {
                float4 t4 = *(const float4*)(addh + (size_t)n*128 + m0);
                ad0 = t4.x; ad1 = t4.y; ad2 = t4.z; ad3 = t4.w;
            } else {
                ad0 = ad1 = ad2 = ad3 = addh[n];
            }
            float4 tg4 = *(float4*)&tg[(nc0+j)*128 + m0];
            float4 sv  = *(const float4*)(s_in + (size_t)n*128 + m0);
            float4 o;
            o.x = (tanh_(a[4*j+0] + ad0) - sv.x) * tg4.x + sv.x;
            o.y = (tanh_(a[4*j+1] + ad1) - sv.y) * tg4.y + sv.y;
            o.z = (tanh_(a[4*j+2] + ad2) - sv.z) * tg4.z + sv.z;
            o.w = (tanh_(a[4*j+3] + ad3) - sv.w) * tg4.w + sv.w;
            *(float4*)(s_out + (size_t)n*128 + m0) = o;
        }
    }
}

// =================================================================================
// Pre kernel: xh = emb[tok]@Wh0x + bh0 ; xt = emb[tok]@Wt0x + bt0, stored [t][r][b].
// Block: 32 rows (rho = t*B+b) x 64 r-cols, both gates. Grid (16, 1024). 256 thr.
// =================================================================================
#define KBP 8
__global__ __launch_bounds__(256, 1) void pre_kernel(
    const int* __restrict__ tok, const float* __restrict__ emb,
    const float* __restrict__ Whx, const float* __restrict__ Wtx,
    const float* __restrict__ bh, const float* __restrict__ bt)
{
    __shared__ float x_sm[NU_*34];     // [k][row], 256 x 32, pitch 34
    __shared__ u64 wh_sm[KBP*64];
    __shared__ u64 wt_sm[KBP*64];

    const int tid  = threadIdx.x;
    const int row0 = blockIdx.y * 32;
    const int n0   = blockIdx.x * 64;

    // gather x tile: 32 rows x 256 k, transposed
    #pragma unroll
    for (int it = 0; it < 8; ++it) {
        int idx = tid + it*256;
        int r = idx >> 6, q = idx & 63;
        int rho = row0 + r;
        int b = rho & (B_-1), t = rho >> 7;
        int token = tok[b*T_ + t];
        float4 v = *(const float4*)(emb + (size_t)token*NU_ + 4*q);
        x_sm[(4*q+0)*34 + r] = v.x;
        x_sm[(4*q+1)*34 + r] = v.y;
        x_sm[(4*q+2)*34 + r] = v.z;
        x_sm[(4*q+3)*34 + r] = v.w;
    }
    __syncthreads();

    const int mp = tid & 15;   // 2 rows each
    const int ng = tid >> 4;   // 0..15 -> 4 cols each
    u64 acch[4] = {0,0,0,0};
    u64 acct[4] = {0,0,0,0};

    for (int k0 = 0; k0 < NU_; k0 += KBP) {
        #pragma unroll
        for (int it = 0; it < 2; ++it) {
            int idx = tid + it*256;
            int kl = idx >> 6, c = idx & 63;
            float wh = Whx[(size_t)(k0+kl)*R_ + n0 + c];
            float wt = Wtx[(size_t)(k0+kl)*R_ + n0 + c];
            wh_sm[kl*64 + c] = pk2(wh, wh);
            wt_sm[kl*64 + c] = pk2(wt, wt);
        }
        __syncthreads();
        #pragma unroll
        for (int kl = 0; kl < KBP; ++kl) {
            u64 x2 = *(const u64*)&x_sm[(k0+kl)*34 + 2*mp];
            ulonglong2 wa = *(const ulonglong2*)&wh_sm[kl*64 + 4*ng];
            ulonglong2 wb = *(const ulonglong2*)&wh_sm[kl*64 + 4*ng + 2];
            ulonglong2 ta = *(const ulonglong2*)&wt_sm[kl*64 + 4*ng];
            ulonglong2 tb = *(const ulonglong2*)&wt_sm[kl*64 + 4*ng + 2];
            fma2(acch[0], x2, wa.x); fma2(acch[1], x2, wa.y);
            fma2(acch[2], x2, wb.x); fma2(acch[3], x2, wb.y);
            fma2(acct[0], x2, ta.x); fma2(acct[1], x2, ta.y);
            fma2(acct[2], x2, tb.x); fma2(acct[3], x2, tb.y);
        }
        __syncthreads();
    }

    // epilogue: write [t][r][b] transposed: idx = t*BR + n*128 + b
    #pragma unroll
    for (int j = 0; j < 4; ++j) {
        int n = n0 + 4*ng + j;
        float lo, hi, tlo, thi;
        up2(lo, hi, acch[j]);
        up2(tlo, thi, acct[j]);
        int rho = row0 + 2*mp;           // even
        int b = rho & (B_-1), t = rho >> 7;
        size_t base = (size_t)t*BR_ + (size_t)n*128 + b;   // b, b+1 same t
        g_xh[base]   = lo  + bh[n];
        g_xh[base+1] = hi  + bh[n];
        g_xt[base]   = tlo + bt[n];
        g_xt[base+1] = thi + bt[n];
    }
}

// =================================================================================
// Post kernel: out[(b*T+t), n] = sum_k hist[t][k][b] * Wp[k][n] + bp[n].
// Block: 32 b-rows x 64 nu-cols for one t. Grid (4, 4, 256). 256 threads.
// =================================================================================
#define KBQ 32
__global__ __launch_bounds__(256, 1) void post_kernel(
    const float* __restrict__ Wp, const float* __restrict__ bp,
    float* __restrict__ out)
{
    __shared__ float s_sm[KBQ*32];   // [k][b] flat copy
    __shared__ u64 w_sm[KBQ*64];

    const int tid = threadIdx.x;
    const int n0  = blockIdx.x * 64;
    const int b0  = blockIdx.y * 32;
    const int t   = blockIdx.z;
    const float* A = g_hist + (size_t)t*BR_;

    const int mp = tid & 15;
    const int ng = tid >> 4;
    u64 acc[4] = {0,0,0,0};

    for (int k0 = 0; k0 < R_; k0 += KBQ) {
        {   // A chunk [32 k][32 b]: 256 float4, one per thread, no transpose
            int kl = tid >> 3, bl = (tid & 7) * 4;
            float4 v = *(const float4*)(A + (size_t)(k0+kl)*128 + b0 + bl);
            *(float4*)&s_sm[kl*32 + bl] = v;
        }
        #pragma unroll
        for (int it = 0; it < 4; ++it) {
            int idx = tid + it*256;
            int kl = idx >> 5, c = idx & 31;
            float2 wv = *(const float2*)(Wp + (size_t)(k0+kl)*NU_ + n0 + 2*c);
            w_sm[kl*64 + 2*c]   = pk2(wv.x, wv.x);
            w_sm[kl*64 + 2*c+1] = pk2(wv.y, wv.y);
        }
        __syncthreads();
        #pragma unroll 8
        for (int kl = 0; kl < KBQ; ++kl) {
            u64 s2 = *(const u64*)&s_sm[kl*32 + 2*mp];
            ulonglong2 wa = *(const ulonglong2*)&w_sm[kl*64 + 4*ng];
            ulonglong2 wb = *(const ulonglong2*)&w_sm[kl*64 + 4*ng + 2];
            fma2(acc[0], s2, wa.x); fma2(acc[1], s2, wa.y);
            fma2(acc[2], s2, wb.x); fma2(acc[3], s2, wb.y);
        }
        __syncthreads();
    }

    #pragma unroll
    for (int j = 0; j < 4; ++j) {
        int n = n0 + 4*ng + j;
        float lo, hi;
        up2(lo, hi, acc[j]);
        int bl = b0 + 2*mp;
        out[(size_t)(bl*T_ + t)*NU_ + n]     = lo + bp[n];
        out[(size_t)((bl+1)*T_ + t)*NU_ + n] = hi + bp[n];
    }
}

// =================================================================================
extern "C" void kernel_launch(void* const* d_in, const int* in_sizes, int n_in,
                              void* d_out, int out_size) {
    const int*   tok  = (const int*)  d_in[0];
    const float* emb  = (const float*)d_in[1];
    const float* Wh0x = (const float*)d_in[2];
    const float* Wh0s = (const float*)d_in[3];
    const float* bh0  = (const float*)d_in[4];
    const float* Wt0x = (const float*)d_in[5];
    const float* Wt0s = (const float*)d_in[6];
    const float* bt0  = (const float*)d_in[7];
    const float* Whh  = (const float*)d_in[8];
    const float* bhh  = (const float*)d_in[9];
    const float* Wth  = (const float*)d_in[10];
    const float* bth  = (const float*)d_in[11];
    const float* Wp   = (const float*)d_in[12];
    const float* bp   = (const float*)d_in[13];

    float *xh, *xt, *hist, *sA, *sB, *s0;
    cudaGetSymbolAddress((void**)&xh,   g_xh);
    cudaGetSymbolAddress((void**)&xt,   g_xt);
    cudaGetSymbolAddress((void**)&hist, g_hist);
    cudaGetSymbolAddress((void**)&sA,   g_sA);
    cudaGetSymbolAddress((void**)&sB,   g_sB);
    cudaGetSymbolAddress((void**)&s0,   g_s0);

    cudaFuncSetAttribute(stage_kernel,
                         cudaFuncAttributeMaxDynamicSharedMemorySize, SM_TOTAL);

    pre_kernel<<<dim3(16, 1024), 256>>>(tok, emb, Wh0x, Wt0x, bh0, bt0);

    const float* sprev = s0;
    for (int t = 0; t < T_; ++t) {
        stage_kernel<<<128, 256, SM_TOTAL>>>(sprev, Wh0s, Wt0s,
                                             xh + (size_t)t*BR_, xt + (size_t)t*BR_,
                                             1, sA);
        stage_kernel<<<128, 256, SM_TOTAL>>>(sA, Whh, Wth, bhh, bth, 0, sB);
        stage_kernel<<<128, 256, SM_TOTAL>>>(sB, Whh + (size_t)R_*R_, Wth + (size_t)R_*R_,
                                             bhh + R_, bth + R_, 0,
                                             hist + (size_t)t*BR_);
        sprev = hist + (size_t)t*BR_;
    }

    post_kernel<<<dim3(4, 4, 256), 256>>>(Wp, bp, (float*)d_out);
}

// round 4
// speedup vs baseline: 1.3706x; 1.0153x over previous
#include <cuda_runtime.h>

#define B_  128
#define T_  256
#define R_  1024
#define NU_ 256
#define BR_ (B_*R_)

// ---------------- static device scratch ----------------
// state tensors TRANSPOSED: [r][b]
__device__ float g_xh[(size_t)T_*BR_];    // [t][r][b]
__device__ float g_xt[(size_t)T_*BR_];    // [t][r][b]
__device__ float g_hist[(size_t)T_*BR_];  // [t][r][b]
__device__ float g_sA[BR_];
__device__ float g_sB[BR_];
__device__ float g_s0[BR_];               // stays zero

typedef unsigned long long u64;

__device__ __forceinline__ u64 pk2(float lo, float hi) {
    u64 r; asm("mov.b64 %0, {%1, %2};" : "=l"(r) : "f"(lo), "f"(hi)); return r;
}
__device__ __forceinline__ void up2(float &lo, float &hi, u64 v) {
    asm("mov.b64 {%0, %1}, %2;" : "=f"(lo), "=f"(hi) : "l"(v));
}
__device__ __forceinline__ void fma2(u64 &d, u64 a, u64 b) {
    asm("fma.rn.f32x2 %0, %1, %2, %0;" : "+l"(d) : "l"(a), "l"(b));
}
__device__ __forceinline__ u64 add2(u64 a, u64 b) {
    u64 r; asm("add.rn.f32x2 %0, %1, %2;" : "=l"(r) : "l"(a), "l"(b)); return r;
}

__device__ __forceinline__ float sigmoid_(float x) {
    return __frcp_rn(1.f + __expf(-x));
}
__device__ __forceinline__ float tanh_(float x) {
    return __fmaf_rn(2.f, __frcp_rn(1.f + __expf(-2.f*x)), -1.f);
}

__device__ __forceinline__ void cp16(unsigned s, const void* g) {
    asm volatile("cp.async.cg.shared.global [%0], [%1], 16;" :: "r"(s), "l"(g));
}
__device__ __forceinline__ void cpcommit() { asm volatile("cp.async.commit_group;"); }
template<int N> __device__ __forceinline__ void cpwait() {
    asm volatile("cp.async.wait_group %0;" :: "n"(N));
}

// =================================================================================
// Stage kernel (k-split): one highway layer, tensors [r][b].
// 512 threads = 16 warps = (khalf 2) x (gate 2) x (mslice 4); 4 warps/SMSP.
// Each warp: 32 m x 8 n, one gate, one 512-k half. Partials reduced via smem.
// Dyn smem: s 4x32KB | w 8x4KB | red 8KB | tg 4KB = 176128 B.
// =================================================================================
#define KC 64                       // k per chunk per half
#define NCH 8                       // chunks per half (512/64)
#define SM_S(h,buf)   (((h)*2+(buf))*32768)
#define SM_W(h,g,buf) (131072 + ((((h)*2+(g))*2+(buf))*4096))
#define SM_RED        163840
#define SM_TG         172032
#define SM_TOTAL      176128

__global__ __launch_bounds__(512, 1) void stage_kernel(
    const float* __restrict__ s_in,
    const float* __restrict__ Wh, const float* __restrict__ Wt,
    const float* __restrict__ addh, const float* __restrict__ addt,
    int per_elem,
    float* __restrict__ s_out)
{
    extern __shared__ char sm[];
    const int tid    = threadIdx.x;
    const int n0     = blockIdx.x * 8;
    const int warp   = tid >> 5, lane = tid & 31;
    const int khalf  = warp >> 3;
    const int gate   = (warp >> 2) & 1;
    const int mslice = warp & 3;
    const int mg     = lane & 7, ng = lane >> 3;
    const int m0     = mslice * 32 + mg * 4;
    const int nc0    = ng * 2;

    const unsigned smb = (unsigned)__cvta_generic_to_shared(sm);

    // w-loader thread mapping: thread covers (wh = tid>>8, kl, cc)
    const int wl_h  = tid >> 8;
    const int wl_kl = (tid & 255) >> 2;
    const int wl_cc = tid & 3;

    // ---- prologue: s chunk0 (both halves) via cp.async; w chunk0 direct ----
    #pragma unroll
    for (int h = 0; h < 2; ++h) {
        const char* g = (const char*)(s_in + (size_t)h*512*128);
        unsigned sb = smb + SM_S(h,0);
        #pragma unroll
        for (int j = 0; j < 4; ++j) {
            int o = (tid + j*512) * 16;
            cp16(sb + o, g + o);
        }
    }
    cpcommit();
    {
        size_t go = (size_t)(wl_h*512 + wl_kl)*R_ + n0 + 2*wl_cc;
        float2 vh = *(const float2*)(Wh + go);
        float2 vt = *(const float2*)(Wt + go);
        ulonglong2 dh; dh.x = pk2(vh.x, vh.x); dh.y = pk2(vh.y, vh.y);
        ulonglong2 dt; dt.x = pk2(vt.x, vt.x); dt.y = pk2(vt.y, vt.y);
        *(ulonglong2*)(sm + SM_W(wl_h,0,0) + (wl_kl*8 + 2*wl_cc)*8) = dh;
        *(ulonglong2*)(sm + SM_W(wl_h,1,0) + (wl_kl*8 + 2*wl_cc)*8) = dt;
    }

    u64 acc0 = 0, acc1 = 0, acc2 = 0, acc3 = 0;
    float2 whr, wtr;

    for (int c = 0; c < NCH; ++c) {
        const int cur = c & 1, nxt = cur ^ 1;
        const bool more = (c + 1 < NCH);
        if (more) {
            #pragma unroll
            for (int h = 0; h < 2; ++h) {
                const char* g = (const char*)(s_in + (size_t)(h*512 + (c+1)*KC)*128);
                unsigned sb = smb + SM_S(h,nxt);
                #pragma unroll
                for (int j = 0; j < 4; ++j) {
                    int o = (tid + j*512) * 16;
                    cp16(sb + o, g + o);
                }
            }
            cpcommit();
            size_t go = (size_t)(wl_h*512 + (c+1)*KC + wl_kl)*R_ + n0 + 2*wl_cc;
            whr = *(const float2*)(Wh + go);
            wtr = *(const float2*)(Wt + go);
        }
        if (more) cpwait<1>(); else cpwait<0>();
        __syncthreads();

        // ---- mainloop: 1 LDS.128 (s) + 1 LDS.128 (w) + 4 FFMA2 per k ----
        {
            const char* sp = sm + SM_S(khalf,cur) + m0*4;
            const char* wp = sm + SM_W(khalf,gate,cur) + nc0*8;
            #pragma unroll 8
            for (int kl = 0; kl < KC; ++kl) {
                ulonglong2 s2 = *(const ulonglong2*)(sp + kl*512);
                ulonglong2 w2 = *(const ulonglong2*)(wp + kl*64);
                fma2(acc0, s2.x, w2.x);
                fma2(acc1, s2.y, w2.x);
                fma2(acc2, s2.x, w2.y);
                fma2(acc3, s2.y, w2.y);
            }
        }
        __syncthreads();

        if (more) {
            ulonglong2 dh; dh.x = pk2(whr.x, whr.x); dh.y = pk2(whr.y, whr.y);
            ulonglong2 dt; dt.x = pk2(wtr.x, wtr.x); dt.y = pk2(wtr.y, wtr.y);
            *(ulonglong2*)(sm + SM_W(wl_h,0,nxt) + (wl_kl*8 + 2*wl_cc)*8) = dh;
            *(ulonglong2*)(sm + SM_W(wl_h,1,nxt) + (wl_kl*8 + 2*wl_cc)*8) = dt;
        }
    }

    // ---- cross-half reduction ----
    u64* red = (u64*)(sm + SM_RED) + ((gate*4 + mslice)*32 + lane)*4;
    if (khalf == 1) {
        red[0] = acc0; red[1] = acc1; red[2] = acc2; red[3] = acc3;
    }
    __syncthreads();
    if (khalf == 0) {
        acc0 = add2(acc0, red[0]);
        acc1 = add2(acc1, red[1]);
        acc2 = add2(acc2, red[2]);
        acc3 = add2(acc3, red[3]);
    }

    // ---- epilogue (khalf 0 only): gate1 sigmoid -> smem; gate0 combines ----
    float a[8];
    up2(a[0], a[1], acc0);   // m0,m0+1   @ n=nc0
    up2(a[2], a[3], acc1);   // m0+2,m0+3 @ n=nc0
    up2(a[4], a[5], acc2);   // m0,m0+1   @ n=nc0+1
    up2(a[6], a[7], acc3);   // m0+2,m0+3 @ n=nc0+1

    float* tg = (float*)(sm + SM_TG);

    if (khalf == 0 && gate == 1) {
        #pragma unroll
        for (int j = 0; j < 2; ++j) {
            int n = n0 + nc0 + j;
            float ad0, ad1, ad2, ad3;
            if (per_elem) {
                float4 t4 = *(const float4*)(addt + (size_t)n*128 + m0);
                ad0 = t4.x; ad1 = t4.y; ad2 = t4.z; ad3 = t4.w;
            } else {
                ad0 = ad1 = ad2 = ad3 = addt[n];
            }
            float4 o;
            o.x = sigmoid_(a[4*j+0] + ad0);
            o.y = sigmoid_(a[4*j+1] + ad1);
            o.z = sigmoid_(a[4*j+2] + ad2);
            o.w = sigmoid_(a[4*j+3] + ad3);
            *(float4*)&tg[(nc0+j)*128 + m0] = o;
        }
    }
    __syncthreads();
    if (khalf == 0 && gate == 0) {
        #pragma unroll
        for (int j = 0; j < 2; ++j) {
            int n = n0 + nc0 + j;
            float ad0, ad1, ad2, ad3;
            if (per_elem) {
                float4 t4 = *(const float4*)(addh + (size_t)n*128 + m0);
                ad0 = t4.x; ad1 = t4.y; ad2 = t4.z; ad3 = t4.w;
            } else {
                ad0 = ad1 = ad2 = ad3 = addh[n];
            }
            float4 tg4 = *(float4*)&tg[(nc0+j)*128 + m0];
            float4 sv  = *(const float4*)(s_in + (size_t)n*128 + m0);
            float4 o;
            o.x = (tanh_(a[4*j+0] + ad0) - sv.x) * tg4.x + sv.x;
            o.y = (tanh_(a[4*j+1] + ad1) - sv.y) * tg4.y + sv.y;
            o.z = (tanh_(a[4*j+2] + ad2) - sv.z) * tg4.z + sv.z;
            o.w = (tanh_(a[4*j+3] + ad3) - sv.w) * tg4.w + sv.w;
            *(float4*)(s_out + (size_t)n*128 + m0) = o;
        }
    }
}

// =================================================================================
// Pre kernel: xh = emb[tok]@Wh0x + bh0 ; xt = emb[tok]@Wt0x + bt0, stored [t][r][b].
// =================================================================================
#define KBP 8
__global__ __launch_bounds__(256, 1) void pre_kernel(
    const int* __restrict__ tok, const float* __restrict__ emb,
    const float* __restrict__ Whx, const float* __restrict__ Wtx,
    const float* __restrict__ bh, const float* __restrict__ bt)
{
    __shared__ float x_sm[NU_*34];
    __shared__ u64 wh_sm[KBP*64];
    __shared__ u64 wt_sm[KBP*64];

    const int tid  = threadIdx.x;
    const int row0 = blockIdx.y * 32;
    const int n0   = blockIdx.x * 64;

    #pragma unroll
    for (int it = 0; it < 8; ++it) {
        int idx = tid + it*256;
        int r = idx >> 6, q = idx & 63;
        int rho = row0 + r;
        int b = rho & (B_-1), t = rho >> 7;
        int token = tok[b*T_ + t];
        float4 v = *(const float4*)(emb + (size_t)token*NU_ + 4*q);
        x_sm[(4*q+0)*34 + r] = v.x;
        x_sm[(4*q+1)*34 + r] = v.y;
        x_sm[(4*q+2)*34 + r] = v.z;
        x_sm[(4*q+3)*34 + r] = v.w;
    }
    __syncthreads();

    const int mp = tid & 15;
    const int ng = tid >> 4;
    u64 acch[4] = {0,0,0,0};
    u64 acct[4] = {0,0,0,0};

    for (int k0 = 0; k0 < NU_; k0 += KBP) {
        #pragma unroll
        for (int it = 0; it < 2; ++it) {
            int idx = tid + it*256;
            int kl = idx >> 6, c = idx & 63;
            float wh = Whx[(size_t)(k0+kl)*R_ + n0 + c];
            float wt = Wtx[(size_t)(k0+kl)*R_ + n0 + c];
            wh_sm[kl*64 + c] = pk2(wh, wh);
            wt_sm[kl*64 + c] = pk2(wt, wt);
        }
        __syncthreads();
        #pragma unroll
        for (int kl = 0; kl < KBP; ++kl) {
            u64 x2 = *(const u64*)&x_sm[(k0+kl)*34 + 2*mp];
            ulonglong2 wa = *(const ulonglong2*)&wh_sm[kl*64 + 4*ng];
            ulonglong2 wb = *(const ulonglong2*)&wh_sm[kl*64 + 4*ng + 2];
            ulonglong2 ta = *(const ulonglong2*)&wt_sm[kl*64 + 4*ng];
            ulonglong2 tb = *(const ulonglong2*)&wt_sm[kl*64 + 4*ng + 2];
            fma2(acch[0], x2, wa.x); fma2(acch[1], x2, wa.y);
            fma2(acch[2], x2, wb.x); fma2(acch[3], x2, wb.y);
            fma2(acct[0], x2, ta.x); fma2(acct[1], x2, ta.y);
            fma2(acct[2], x2, tb.x); fma2(acct[3], x2, tb.y);
        }
        __syncthreads();
    }

    #pragma unroll
    for (int j = 0; j < 4; ++j) {
        int n = n0 + 4*ng + j;
        float lo, hi, tlo, thi;
        up2(lo, hi, acch[j]);
        up2(tlo, thi, acct[j]);
        int rho = row0 + 2*mp;
        int b = rho & (B_-1), t = rho >> 7;
        size_t base = (size_t)t*BR_ + (size_t)n*128 + b;
        g_xh[base]   = lo  + bh[n];
        g_xh[base+1] = hi  + bh[n];
        g_xt[base]   = tlo + bt[n];
        g_xt[base+1] = thi + bt[n];
    }
}

// =================================================================================
// Post kernel: out[(b*T+t), n] = sum_k hist[t][k][b] * Wp[k][n] + bp[n].
// =================================================================================
#define KBQ 32
__global__ __launch_bounds__(256, 1) void post_kernel(
    const float* __restrict__ Wp, const float* __restrict__ bp,
    float* __restrict__ out)
{
    __shared__ float s_sm[KBQ*32];
    __shared__ u64 w_sm[KBQ*64];

    const int tid = threadIdx.x;
    const int n0  = blockIdx.x * 64;
    const int b0  = blockIdx.y * 32;
    const int t   = blockIdx.z;
    const float* A = g_hist + (size_t)t*BR_;

    const int mp = tid & 15;
    const int ng = tid >> 4;
    u64 acc[4] = {0,0,0,0};

    for (int k0 = 0; k0 < R_; k0 += KBQ) {
        {
            int kl = tid >> 3, bl = (tid & 7) * 4;
            float4 v = *(const float4*)(A + (size_t)(k0+kl)*128 + b0 + bl);
            *(float4*)&s_sm[kl*32 + bl] = v;
        }
        #pragma unroll
        for (int it = 0; it < 4; ++it) {
            int idx = tid + it*256;
            int kl = idx >> 5, c = idx & 31;
            float2 wv = *(const float2*)(Wp + (size_t)(k0+kl)*NU_ + n0 + 2*c);
            w_sm[kl*64 + 2*c]   = pk2(wv.x, wv.x);
            w_sm[kl*64 + 2*c+1] = pk2(wv.y, wv.y);
        }
        __syncthreads();
        #pragma unroll 8
        for (int kl = 0; kl < KBQ; ++kl) {
            u64 s2 = *(const u64*)&s_sm[kl*32 + 2*mp];
            ulonglong2 wa = *(const ulonglong2*)&w_sm[kl*64 + 4*ng];
            ulonglong2 wb = *(const ulonglong2*)&w_sm[kl*64 + 4*ng + 2];
            fma2(acc[0], s2, wa.x); fma2(acc[1], s2, wa.y);
            fma2(acc[2], s2, wb.x); fma2(acc[3], s2, wb.y);
        }
        __syncthreads();
    }

    #pragma unroll
    for (int j = 0; j < 4; ++j) {
        int n = n0 + 4*ng + j;
        float lo, hi;
        up2(lo, hi, acc[j]);
        int bl = b0 + 2*mp;
        out[(size_t)(bl*T_ + t)*NU_ + n]     = lo + bp[n];
        out[(size_t)((bl+1)*T_ + t)*NU_ + n] = hi + bp[n];
    }
}

// =================================================================================
extern "C" void kernel_launch(void* const* d_in, const int* in_sizes, int n_in,
                              void* d_out, int out_size) {
    const int*   tok  = (const int*)  d_in[0];
    const float* emb  = (const float*)d_in[1];
    const float* Wh0x = (const float*)d_in[2];
    const float* Wh0s = (const float*)d_in[3];
    const float* bh0  = (const float*)d_in[4];
    const float* Wt0x = (const float*)d_in[5];
    const float* Wt0s = (const float*)d_in[6];
    const float* bt0  = (const float*)d_in[7];
    const float* Whh  = (const float*)d_in[8];
    const float* bhh  = (const float*)d_in[9];
    const float* Wth  = (const float*)d_in[10];
    const float* bth  = (const float*)d_in[11];
    const float* Wp   = (const float*)d_in[12];
    const float* bp   = (const float*)d_in[13];

    float *xh, *xt, *hist, *sA, *sB, *s0;
    cudaGetSymbolAddress((void**)&xh,   g_xh);
    cudaGetSymbolAddress((void**)&xt,   g_xt);
    cudaGetSymbolAddress((void**)&hist, g_hist);
    cudaGetSymbolAddress((void**)&sA,   g_sA);
    cudaGetSymbolAddress((void**)&sB,   g_sB);
    cudaGetSymbolAddress((void**)&s0,   g_s0);

    cudaFuncSetAttribute(stage_kernel,
                         cudaFuncAttributeMaxDynamicSharedMemorySize, SM_TOTAL);

    pre_kernel<<<dim3(16, 1024), 256>>>(tok, emb, Wh0x, Wt0x, bh0, bt0);

    const float* sprev = s0;
    for (int t = 0; t < T_; ++t) {
        stage_kernel<<<128, 512, SM_TOTAL>>>(sprev, Wh0s, Wt0s,
                                             xh + (size_t)t*BR_, xt + (size_t)t*BR_,
                                             1, sA);
        stage_kernel<<<128, 512, SM_TOTAL>>>(sA, Whh, Wth, bhh, bth, 0, sB);
        stage_kernel<<<128, 512, SM_TOTAL>>>(sB, Whh + (size_t)R_*R_, Wth + (size_t)R_*R_,
                                             bhh + R_, bth + R_, 0,
                                             hist + (size_t)t*BR_);
        sprev = hist + (size_t)t*BR_;
    }

    post_kernel<<<dim3(4, 4, 256), 256>>>(Wp, bp, (float*)d_out);
}

// round 5
// speedup vs baseline: 1.7509x; 1.2775x over previous
#include <cuda_runtime.h>

#define B_  128
#define T_  256
#define R_  1024
#define NU_ 256
#define BR_ (B_*R_)

// ---------------- static device scratch ----------------
// state tensors TRANSPOSED: [r][b]
__device__ float g_xh[(size_t)T_*BR_];    // [t][r][b]
__device__ float g_xt[(size_t)T_*BR_];    // [t][r][b]
__device__ float g_hist[(size_t)T_*BR_];  // [t][r][b]
__device__ float g_sA[BR_];
__device__ float g_sB[BR_];
__device__ float g_s0[BR_];               // stays zero

typedef unsigned long long u64;

__device__ __forceinline__ u64 pk2(float lo, float hi) {
    u64 r; asm("mov.b64 %0, {%1, %2};" : "=l"(r) : "f"(lo), "f"(hi)); return r;
}
__device__ __forceinline__ void up2(float &lo, float &hi, u64 v) {
    asm("mov.b64 {%0, %1}, %2;" : "=f"(lo), "=f"(hi) : "l"(v));
}
__device__ __forceinline__ void fma2(u64 &d, u64 a, u64 b) {
    asm("fma.rn.f32x2 %0, %1, %2, %0;" : "+l"(d) : "l"(a), "l"(b));
}
__device__ __forceinline__ u64 add2(u64 a, u64 b) {
    u64 r; asm("add.rn.f32x2 %0, %1, %2;" : "=l"(r) : "l"(a), "l"(b)); return r;
}

__device__ __forceinline__ float sigmoid_(float x) {
    return __frcp_rn(1.f + __expf(-x));
}
__device__ __forceinline__ float tanh_(float x) {
    return __fmaf_rn(2.f, __frcp_rn(1.f + __expf(-2.f*x)), -1.f);
}

__device__ __forceinline__ void cp16(unsigned s, const void* g) {
    asm volatile("cp.async.cg.shared.global [%0], [%1], 16;" :: "r"(s), "l"(g));
}
__device__ __forceinline__ void cpcommit() { asm volatile("cp.async.commit_group;"); }
template<int N> __device__ __forceinline__ void cpwait() {
    asm volatile("cp.async.wait_group %0;" :: "n"(N));
}

// =================================================================================
// Stage kernel: one highway layer, tensors [r][b].
// 256 threads = 8 warps = (kq 4) x (gate 2). Warp covers the FULL 128m x 8n tile
// of its gate for its 256-k quarter (thread tile 8m x 4n; m split mA=mg*4, mB=64+mg*4).
// Per k per thread: 2 LDS.128 (s) + 1 LDS.128 (w plain) + 4 mov dup + 16 FFMA2.
// Weights fully resident in smem (64 KB). s: 4 quarters x 2 bufs x 16 KB stream.
// Dyn smem: s 128 KB | wh 32 KB | wt 32 KB = 192 KB. red/tg alias s q0/q1.
// =================================================================================
#define KC 32                        // k per chunk per quarter
#define NCH 8                        // chunks per quarter (256/32)
#define SM_S(q,buf)  ((((q)*2)+(buf))*16384)
#define SM_WH        131072
#define SM_WT        163840
#define SM_RED       0               // aliases s q0 (free after mainloop)
#define SM_TG        32768           // aliases s q1
#define SM_TOTAL     196608

__global__ __launch_bounds__(256, 1) void stage_kernel(
    const float* __restrict__ s_in,
    const float* __restrict__ Wh, const float* __restrict__ Wt,
    const float* __restrict__ addh, const float* __restrict__ addt,
    int per_elem,
    float* __restrict__ s_out)
{
    extern __shared__ char sm[];
    const int tid  = threadIdx.x;
    const int n0   = blockIdx.x * 8;
    const int warp = tid >> 5, lane = tid & 31;
    const int kq   = warp >> 1, gate = warp & 1;
    const int mg   = lane & 15, ng = lane >> 4;
    const int mA   = mg * 4;          // m-quad A
    const int mB   = 64 + mg * 4;     // m-quad B
    const unsigned smb = (unsigned)__cvta_generic_to_shared(sm);

    // ---- prologue: full weights (64 KB) + s chunk0 for all 4 quarters ----
    #pragma unroll
    for (int it = 0; it < 8; ++it) {
        int idx = tid + it*256;            // 0..2047
        int k = idx >> 1, half = idx & 1;
        cp16(smb + SM_WH + k*32 + half*16, Wh + (size_t)k*R_ + n0 + half*4);
        cp16(smb + SM_WT + k*32 + half*16, Wt + (size_t)k*R_ + n0 + half*4);
    }
    #pragma unroll
    for (int q = 0; q < 4; ++q) {
        const char* g = (const char*)(s_in + (size_t)q*256*128);
        unsigned sb = smb + SM_S(q,0);
        #pragma unroll
        for (int j = 0; j < 4; ++j) {
            int o = (tid + j*256) * 16;
            cp16(sb + o, g + o);
        }
    }
    cpcommit();

    u64 acc[16];
    #pragma unroll
    for (int a = 0; a < 16; ++a) acc[a] = 0;

    const char* wbase = sm + (gate ? SM_WT : SM_WH) + ng*16;

    for (int c = 0; c < NCH; ++c) {
        const int cur = c & 1, nxt = cur ^ 1;
        const bool more = (c + 1 < NCH);
        if (more) {
            #pragma unroll
            for (int q = 0; q < 4; ++q) {
                const char* g = (const char*)(s_in + (size_t)(q*256 + (c+1)*KC)*128);
                unsigned sb = smb + SM_S(q,nxt);
                #pragma unroll
                for (int j = 0; j < 4; ++j) {
                    int o = (tid + j*256) * 16;
                    cp16(sb + o, g + o);
                }
            }
            cpcommit();
            cpwait<1>();
        } else {
            cpwait<0>();
        }
        __syncthreads();

        // ---- mainloop: 3 LDS.128 + 4 MOV + 16 FFMA2 per k per thread ----
        const char* sp = sm + SM_S(kq,cur) + mg*16;
        const char* wp = wbase + (size_t)(kq*256 + c*KC)*32;
        #pragma unroll 8
        for (int kl = 0; kl < KC; ++kl) {
            ulonglong2 sA = *(const ulonglong2*)(sp + kl*512);
            ulonglong2 sB = *(const ulonglong2*)(sp + kl*512 + 256);
            float4 w4 = *(const float4*)(wp + kl*32);
            u64 w0 = pk2(w4.x, w4.x), w1 = pk2(w4.y, w4.y);
            u64 w2 = pk2(w4.z, w4.z), w3 = pk2(w4.w, w4.w);
            fma2(acc[0],  sA.x, w0); fma2(acc[1],  sA.y, w0);
            fma2(acc[2],  sB.x, w0); fma2(acc[3],  sB.y, w0);
            fma2(acc[4],  sA.x, w1); fma2(acc[5],  sA.y, w1);
            fma2(acc[6],  sB.x, w1); fma2(acc[7],  sB.y, w1);
            fma2(acc[8],  sA.x, w2); fma2(acc[9],  sA.y, w2);
            fma2(acc[10], sB.x, w2); fma2(acc[11], sB.y, w2);
            fma2(acc[12], sA.x, w3); fma2(acc[13], sA.y, w3);
            fma2(acc[14], sB.x, w3); fma2(acc[15], sB.y, w3);
        }
        __syncthreads();
    }

    // ---- cross-quarter reduction (red aliases s q0, free now) ----
    u64* red = (u64*)(sm + SM_RED);
    if (kq > 0) {
        u64* dst = red + (size_t)(((kq-1)*2 + gate)*32 + lane)*16;
        #pragma unroll
        for (int a = 0; a < 16; ++a) dst[a] = acc[a];
    }
    __syncthreads();
    if (kq == 0) {
        #pragma unroll
        for (int r = 0; r < 3; ++r) {
            const u64* src = red + (size_t)((r*2 + gate)*32 + lane)*16;
            #pragma unroll
            for (int a = 0; a < 16; ++a) acc[a] = add2(acc[a], src[a]);
        }
    }

    // ---- epilogue: gate1 sigmoid -> tg; gate0 combines (kq0 warps only) ----
    float* tg = (float*)(sm + SM_TG);
    if (kq == 0 && gate == 1) {
        #pragma unroll
        for (int j = 0; j < 4; ++j) {
            int n = n0 + ng*4 + j;
            float v[8];
            up2(v[0], v[1], acc[j*4+0]); up2(v[2], v[3], acc[j*4+1]);
            up2(v[4], v[5], acc[j*4+2]); up2(v[6], v[7], acc[j*4+3]);
            float4 tA, tB;
            if (per_elem) {
                tA = *(const float4*)(addt + (size_t)n*128 + mA);
                tB = *(const float4*)(addt + (size_t)n*128 + mB);
            } else {
                float bv = addt[n];
                tA = make_float4(bv, bv, bv, bv); tB = tA;
            }
            float4 oA, oB;
            oA.x = sigmoid_(v[0] + tA.x); oA.y = sigmoid_(v[1] + tA.y);
            oA.z = sigmoid_(v[2] + tA.z); oA.w = sigmoid_(v[3] + tA.w);
            oB.x = sigmoid_(v[4] + tB.x); oB.y = sigmoid_(v[5] + tB.y);
            oB.z = sigmoid_(v[6] + tB.z); oB.w = sigmoid_(v[7] + tB.w);
            *(float4*)&tg[(ng*4+j)*128 + mA] = oA;
            *(float4*)&tg[(ng*4+j)*128 + mB] = oB;
        }
    }
    __syncthreads();
    if (kq == 0 && gate == 0) {
        #pragma unroll
        for (int j = 0; j < 4; ++j) {
            int n = n0 + ng*4 + j;
            float v[8];
            up2(v[0], v[1], acc[j*4+0]); up2(v[2], v[3], acc[j*4+1]);
            up2(v[4], v[5], acc[j*4+2]); up2(v[6], v[7], acc[j*4+3]);
            float4 hA, hB;
            if (per_elem) {
                hA = *(const float4*)(addh + (size_t)n*128 + mA);
                hB = *(const float4*)(addh + (size_t)n*128 + mB);
            } else {
                float bv = addh[n];
                hA = make_float4(bv, bv, bv, bv); hB = hA;
            }
            float4 tgA = *(float4*)&tg[(ng*4+j)*128 + mA];
            float4 tgB = *(float4*)&tg[(ng*4+j)*128 + mB];
            float4 svA = *(const float4*)(s_in + (size_t)n*128 + mA);
            float4 svB = *(const float4*)(s_in + (size_t)n*128 + mB);
            float4 oA, oB;
            oA.x = (tanh_(v[0] + hA.x) - svA.x) * tgA.x + svA.x;
            oA.y = (tanh_(v[1] + hA.y) - svA.y) * tgA.y + svA.y;
            oA.z = (tanh_(v[2] + hA.z) - svA.z) * tgA.z + svA.z;
            oA.w = (tanh_(v[3] + hA.w) - svA.w) * tgA.w + svA.w;
            oB.x = (tanh_(v[4] + hB.x) - svB.x) * tgB.x + svB.x;
            oB.y = (tanh_(v[5] + hB.y) - svB.y) * tgB.y + svB.y;
            oB.z = (tanh_(v[6] + hB.z) - svB.z) * tgB.z + svB.z;
            oB.w = (tanh_(v[7] + hB.w) - svB.w) * tgB.w + svB.w;
            *(float4*)(s_out + (size_t)n*128 + mA) = oA;
            *(float4*)(s_out + (size_t)n*128 + mB) = oB;
        }
    }
}

// =================================================================================
// Pre kernel: xh = emb[tok]@Wh0x + bh0 ; xt = emb[tok]@Wt0x + bt0, stored [t][r][b].
// =================================================================================
#define KBP 8
__global__ __launch_bounds__(256, 1) void pre_kernel(
    const int* __restrict__ tok, const float* __restrict__ emb,
    const float* __restrict__ Whx, const float* __restrict__ Wtx,
    const float* __restrict__ bh, const float* __restrict__ bt)
{
    __shared__ float x_sm[NU_*34];
    __shared__ u64 wh_sm[KBP*64];
    __shared__ u64 wt_sm[KBP*64];

    const int tid  = threadIdx.x;
    const int row0 = blockIdx.y * 32;
    const int n0   = blockIdx.x * 64;

    #pragma unroll
    for (int it = 0; it < 8; ++it) {
        int idx = tid + it*256;
        int r = idx >> 6, q = idx & 63;
        int rho = row0 + r;
        int b = rho & (B_-1), t = rho >> 7;
        int token = tok[b*T_ + t];
        float4 v = *(const float4*)(emb + (size_t)token*NU_ + 4*q);
        x_sm[(4*q+0)*34 + r] = v.x;
        x_sm[(4*q+1)*34 + r] = v.y;
        x_sm[(4*q+2)*34 + r] = v.z;
        x_sm[(4*q+3)*34 + r] = v.w;
    }
    __syncthreads();

    const int mp = tid & 15;
    const int ng = tid >> 4;
    u64 acch[4] = {0,0,0,0};
    u64 acct[4] = {0,0,0,0};

    for (int k0 = 0; k0 < NU_; k0 += KBP) {
        #pragma unroll
        for (int it = 0; it < 2; ++it) {
            int idx = tid + it*256;
            int kl = idx >> 6, c = idx & 63;
            float wh = Whx[(size_t)(k0+kl)*R_ + n0 + c];
            float wt = Wtx[(size_t)(k0+kl)*R_ + n0 + c];
            wh_sm[kl*64 + c] = pk2(wh, wh);
            wt_sm[kl*64 + c] = pk2(wt, wt);
        }
        __syncthreads();
        #pragma unroll
        for (int kl = 0; kl < KBP; ++kl) {
            u64 x2 = *(const u64*)&x_sm[(k0+kl)*34 + 2*mp];
            ulonglong2 wa = *(const ulonglong2*)&wh_sm[kl*64 + 4*ng];
            ulonglong2 wb = *(const ulonglong2*)&wh_sm[kl*64 + 4*ng + 2];
            ulonglong2 ta = *(const ulonglong2*)&wt_sm[kl*64 + 4*ng];
            ulonglong2 tb = *(const ulonglong2*)&wt_sm[kl*64 + 4*ng + 2];
            fma2(acch[0], x2, wa.x); fma2(acch[1], x2, wa.y);
            fma2(acch[2], x2, wb.x); fma2(acch[3], x2, wb.y);
            fma2(acct[0], x2, ta.x); fma2(acct[1], x2, ta.y);
            fma2(acct[2], x2, tb.x); fma2(acct[3], x2, tb.y);
        }
        __syncthreads();
    }

    #pragma unroll
    for (int j = 0; j < 4; ++j) {
        int n = n0 + 4*ng + j;
        float lo, hi, tlo, thi;
        up2(lo, hi, acch[j]);
        up2(tlo, thi, acct[j]);
        int rho = row0 + 2*mp;
        int b = rho & (B_-1), t = rho >> 7;
        size_t base = (size_t)t*BR_ + (size_t)n*128 + b;
        g_xh[base]   = lo  + bh[n];
        g_xh[base+1] = hi  + bh[n];
        g_xt[base]   = tlo + bt[n];
        g_xt[base+1] = thi + bt[n];
    }
}

// =================================================================================
// Post kernel: out[(b*T+t), n] = sum_k hist[t][k][b] * Wp[k][n] + bp[n].
// =================================================================================
#define KBQ 32
__global__ __launch_bounds__(256, 1) void post_kernel(
    const float* __restrict__ Wp, const float* __restrict__ bp,
    float* __restrict__ out)
{
    __shared__ float s_sm[KBQ*32];
    __shared__ u64 w_sm[KBQ*64];

    const int tid = threadIdx.x;
    const int n0  = blockIdx.x * 64;
    const int b0  = blockIdx.y * 32;
    const int t   = blockIdx.z;
    const float* A = g_hist + (size_t)t*BR_;

    const int mp = tid & 15;
    const int ng = tid >> 4;
    u64 acc[4] = {0,0,0,0};

    for (int k0 = 0; k0 < R_; k0 += KBQ) {
        {
            int kl = tid >> 3, bl = (tid & 7) * 4;
            float4 v = *(const float4*)(A + (size_t)(k0+kl)*128 + b0 + bl);
            *(float4*)&s_sm[kl*32 + bl] = v;
        }
        #pragma unroll
        for (int it = 0; it < 4; ++it) {
            int idx = tid + it*256;
            int kl = idx >> 5, c = idx & 31;
            float2 wv = *(const float2*)(Wp + (size_t)(k0+kl)*NU_ + n0 + 2*c);
            w_sm[kl*64 + 2*c]   = pk2(wv.x, wv.x);
            w_sm[kl*64 + 2*c+1] = pk2(wv.y, wv.y);
        }
        __syncthreads();
        #pragma unroll 8
        for (int kl = 0; kl < KBQ; ++kl) {
            u64 s2 = *(const u64*)&s_sm[kl*32 + 2*mp];
            ulonglong2 wa = *(const ulonglong2*)&w_sm[kl*64 + 4*ng];
            ulonglong2 wb = *(const ulonglong2*)&w_sm[kl*64 + 4*ng + 2];
            fma2(acc[0], s2, wa.x); fma2(acc[1], s2, wa.y);
            fma2(acc[2], s2, wb.x); fma2(acc[3], s2, wb.y);
        }
        __syncthreads();
    }

    #pragma unroll
    for (int j = 0; j < 4; ++j) {
        int n = n0 + 4*ng + j;
        float lo, hi;
        up2(lo, hi, acc[j]);
        int bl = b0 + 2*mp;
        out[(size_t)(bl*T_ + t)*NU_ + n]     = lo + bp[n];
        out[(size_t)((bl+1)*T_ + t)*NU_ + n] = hi + bp[n];
    }
}

// =================================================================================
extern "C" void kernel_launch(void* const* d_in, const int* in_sizes, int n_in,
                              void* d_out, int out_size) {
    const int*   tok  = (const int*)  d_in[0];
    const float* emb  = (const float*)d_in[1];
    const float* Wh0x = (const float*)d_in[2];
    const float* Wh0s = (const float*)d_in[3];
    const float* bh0  = (const float*)d_in[4];
    const float* Wt0x = (const float*)d_in[5];
    const float* Wt0s = (const float*)d_in[6];
    const float* bt0  = (const float*)d_in[7];
    const float* Whh  = (const float*)d_in[8];
    const float* bhh  = (const float*)d_in[9];
    const float* Wth  = (const float*)d_in[10];
    const float* bth  = (const float*)d_in[11];
    const float* Wp   = (const float*)d_in[12];
    const float* bp   = (const float*)d_in[13];

    float *xh, *xt, *hist, *sA, *sB, *s0;
    cudaGetSymbolAddress((void**)&xh,   g_xh);
    cudaGetSymbolAddress((void**)&xt,   g_xt);
    cudaGetSymbolAddress((void**)&hist, g_hist);
    cudaGetSymbolAddress((void**)&sA,   g_sA);
    cudaGetSymbolAddress((void**)&sB,   g_sB);
    cudaGetSymbolAddress((void**)&s0,   g_s0);

    cudaFuncSetAttribute(stage_kernel,
                         cudaFuncAttributeMaxDynamicSharedMemorySize, SM_TOTAL);

    pre_kernel<<<dim3(16, 1024), 256>>>(tok, emb, Wh0x, Wt0x, bh0, bt0);

    const float* sprev = s0;
    for (int t = 0; t < T_; ++t) {
        stage_kernel<<<128, 256, SM_TOTAL>>>(sprev, Wh0s, Wt0s,
                                             xh + (size_t)t*BR_, xt + (size_t)t*BR_,
                                             1, sA);
        stage_kernel<<<128, 256, SM_TOTAL>>>(sA, Whh, Wth, bhh, bth, 0, sB);
        stage_kernel<<<128, 256, SM_TOTAL>>>(sB, Whh + (size_t)R_*R_, Wth + (size_t)R_*R_,
                                             bhh + R_, bth + R_, 0,
                                             hist + (size_t)t*BR_);
        sprev = hist + (size_t)t*BR_;
    }

    post_kernel<<<dim3(4, 4, 256), 256>>>(Wp, bp, (float*)d_out);
}